// round 5
// baseline (speedup 1.0000x reference)
#include <cuda_runtime.h>
#include <math.h>

#define Bv 16
#define Tv 256
#define Hv 512
#define Vv 32
#define NBLK 128
#define NTHR 256

// smem layout (floats)
#define SM_XQ   0
#define SM_RED  25664            // 16*1604 (P3 xq: 16 rows * 401 float4)
#define SM_SG   (25664+4096)
#define SM_SQ   (SM_SG+256)
#define SM_SV   (SM_SQ+512)
#define SM_SW   (SM_SV+512)
#define SM_SST  (SM_SW+32)
#define SMEM_FLOATS (SM_SST+2)

typedef unsigned long long ull;

__device__ float g_W0[2048*1536];     // [Wih0 | Whh0]
__device__ float g_W1[2048*1024];     // [Wih1 | Whh1]
__device__ float g_Kproj[Bv*Tv*Hv];
__device__ float g_qp[Bv*Hv];
__device__ float g_scores[Bv*Tv];
__device__ float g_ctx[2][Bv*Hv];
__device__ float g_h[2][2][Bv*Hv];    // [layer][parity][b*H+h]
__device__ unsigned g_flags[NBLK];
__device__ unsigned g_subf[Bv][8];

__device__ __forceinline__ float warp_sum(float v){
#pragma unroll
    for(int o=16;o>0;o>>=1) v += __shfl_xor_sync(0xffffffffu,v,o);
    return v;
}
__device__ __forceinline__ float warp_max(float v){
#pragma unroll
    for(int o=16;o>0;o>>=1) v = fmaxf(v,__shfl_xor_sync(0xffffffffu,v,o));
    return v;
}
__device__ __forceinline__ float sigf(float x){ return 1.0f/(1.0f+expf(-x)); }
__device__ __forceinline__ float tanha(float x){ float y; asm("tanh.approx.f32 %0,%1;":"=f"(y):"f"(x)); return y; }
__device__ __forceinline__ void fma2(ull& acc, ull a, ull b){
    asm("fma.rn.f32x2 %0,%1,%2,%0;" : "+l"(acc) : "l"(a), "l"(b));
}
__device__ __forceinline__ float unpack_add(ull a){
    float lo,hi; asm("mov.b64 {%0,%1},%2;":"=f"(lo),"=f"(hi):"l"(a));
    return lo+hi;
}
__device__ __forceinline__ unsigned ld_acq(const unsigned* p){
    unsigned v; asm volatile("ld.acquire.gpu.u32 %0,[%1];":"=r"(v):"l"(p):"memory"); return v;
}
__device__ __forceinline__ void st_rlx(unsigned* p, unsigned v){
    asm volatile("st.relaxed.gpu.u32 [%0],%1;"::"l"(p),"r"(v):"memory");
}

// flag-array grid barrier: contention-free arrival, direct polling
__device__ __forceinline__ void grid_barrier(unsigned k, int tid, int blk){
    __syncthreads();
    if(tid==0){ __threadfence(); st_rlx(&g_flags[blk], k); }
    if(tid<32){
        const unsigned* f = g_flags + tid*4;
        for(;;){
            unsigned a=ld_acq(f), b=ld_acq(f+1), c=ld_acq(f+2), d=ld_acq(f+3);
            if(a>=k && b>=k && c>=k && d>=k) break;
            __nanosleep(20);
        }
    }
    __syncthreads();
}
__device__ __forceinline__ void sub_barrier(unsigned k, int tid, int ab, int sub){
    __syncthreads();
    if(tid==0){ __threadfence(); st_rlx(&g_subf[ab][sub], k); }
    if(tid<8){
        const unsigned* f = &g_subf[ab][tid];
        while(ld_acq(f)<k) __nanosleep(20);
    }
    __syncthreads();
}

// ---------- one-time: concatenate LSTM weights ----------
__global__ void wcat_kernel(const float* __restrict__ Wih0, const float* __restrict__ Whh0,
                            const float* __restrict__ Wih1, const float* __restrict__ Whh1){
    const int row = blockIdx.x, tid = threadIdx.x;
    const float4* a0 = (const float4*)(Wih0 + (size_t)row*1024);
    const float4* b0 = (const float4*)(Whh0 + (size_t)row*512);
    float4* d0 = (float4*)(g_W0 + (size_t)row*1536);
#pragma unroll
    for(int i=0;i<2;i++) d0[tid+i*128] = a0[tid+i*128];
    d0[256+tid] = b0[tid];
    const float4* a1 = (const float4*)(Wih1 + (size_t)row*512);
    const float4* b1 = (const float4*)(Whh1 + (size_t)row*512);
    float4* d1 = (float4*)(g_W1 + (size_t)row*1024);
    d1[tid]     = a1[tid];
    d1[128+tid] = b1[tid];
}

// ---------- Kproj = enc @ Wk^T + bk ----------
__global__ void kproj_kernel(const float* __restrict__ enc, const float* __restrict__ Wk,
                             const float* __restrict__ bk){
    __shared__ float As[16][65], Bs[16][65];
    const int bm = blockIdx.x*64, bn = blockIdx.y*64, tid = threadIdx.x;
    const int tm = (tid/16)*4, tn = (tid%16)*4;
    float acc[4][4] = {};
    for(int k0=0;k0<Hv;k0+=16){
        for(int i=tid;i<64*16;i+=NTHR){
            int m=i>>4,k=i&15;
            As[k][m]=enc[(size_t)(bm+m)*Hv+k0+k];
            Bs[k][m]=Wk [(size_t)(bn+m)*Hv+k0+k];
        }
        __syncthreads();
#pragma unroll
        for(int k=0;k<16;k++){
            float a[4],b[4];
#pragma unroll
            for(int x=0;x<4;x++){ a[x]=As[k][tm+x]; b[x]=Bs[k][tn+x]; }
#pragma unroll
            for(int x=0;x<4;x++)
#pragma unroll
                for(int y=0;y<4;y++) acc[x][y]+=a[x]*b[y];
        }
        __syncthreads();
    }
#pragma unroll
    for(int x=0;x<4;x++)
#pragma unroll
        for(int y=0;y<4;y++)
            g_Kproj[(size_t)(bm+tm+x)*Hv+bn+tn+y]=acc[x][y]+bk[bn+tn+y];
}

// ---------- init ----------
__global__ void decoder_init(const float* __restrict__ h0in,
                             const float* __restrict__ Wq, const float* __restrict__ bq){
    const int tid=threadIdx.x, blk=blockIdx.x, gid=blk*NTHR+tid;
    if(gid<Bv*Hv){
        g_h[0][0][gid]=h0in[gid];
        g_h[1][0][gid]=h0in[Bv*Hv+gid];
        g_ctx[0][gid]=0.f; g_ctx[1][gid]=0.f;
    }
    if(gid<NBLK) g_flags[gid]=0u;
    if(gid<Bv*8) g_subf[gid>>3][gid&7]=0u;
    const int ab=blk>>3, sub=blk&7, wid=tid>>5, lane=tid&31;
    const float4* h14=(const float4*)(h0in+Bv*Hv+ab*Hv);
#pragma unroll
    for(int r=0;r<8;r++){
        const int hrow=sub*64+r*8+wid;
        const float4* wr=(const float4*)(Wq+(size_t)hrow*Hv);
        float acc=0.f;
#pragma unroll
        for(int i=0;i<4;i++){
            float4 w4=wr[i*32+lane], x4=h14[i*32+lane];
            acc+=w4.x*x4.x+w4.y*x4.y+w4.z*x4.z+w4.w*x4.w;
        }
        acc=warp_sum(acc);
        if(lane==0) g_qp[ab*Hv+hrow]=acc+bq[hrow];
    }
}

// ---------- persistent decoder ----------
__global__ void __launch_bounds__(NTHR,1)
decoder_main(const float* __restrict__ enc, const float* __restrict__ c0in,
             const float* __restrict__ Wq, const float* __restrict__ bq,
             const float* __restrict__ v,  const float* __restrict__ vb,
             const float* __restrict__ bih0, const float* __restrict__ bhh0,
             const float* __restrict__ bih1, const float* __restrict__ bhh1,
             const float* __restrict__ Wout, const float* __restrict__ bout,
             float* __restrict__ out){
    extern __shared__ float sm[];
    float4* xq4 = (float4*)(sm + SM_XQ);
    ull* xqu = (ull*)(sm + SM_XQ);

    const int tid=threadIdx.x, blk=blockIdx.x;
    const int wid=tid>>5, lane=tid&31;
    const int ab=blk>>3, sub=blk&7, t0=sub*32;
    unsigned bar_k=1, sub_k=1;

    sm[SM_SV+tid]=v[tid]; sm[SM_SV+tid+256]=v[tid+256];
    const float vb0=vb[0];

    const int kc = tid>>4, rg = (tid>>2)&3, bg = tid&3;
    const int ul64=tid>>4, b64=tid&15, unit64=blk*4+ul64;
    float c0r=0.f, c1r=0.f;
    if(tid<64){
        c0r=c0in[b64*Hv+unit64];
        c1r=c0in[Bv*Hv+b64*Hv+unit64];
    }

    for(int s=0;s<Tv;s++){
        const int p=s&1, pn=p^1;

        // ======== P1: attention scores (ab, t0..t0+31) ========
        sm[SM_SQ+tid]=g_qp[ab*Hv+tid]; sm[SM_SQ+tid+256]=g_qp[ab*Hv+256+tid];
        __syncthreads();
        {
            const float4* sq4=(const float4*)(sm+SM_SQ);
            const float4* sv4=(const float4*)(sm+SM_SV);
#pragma unroll
            for(int r=0;r<4;r++){
                const int t_=t0+r*8+wid;
                const float4* kp4=(const float4*)(g_Kproj+(size_t)(ab*Tv+t_)*Hv);
                float acc=0.f;
#pragma unroll
                for(int i=0;i<4;i++){
                    float4 k4=kp4[i*32+lane], q4=sq4[i*32+lane], vv=sv4[i*32+lane];
                    acc+=vv.x*tanha(q4.x+k4.x)+vv.y*tanha(q4.y+k4.y)
                        +vv.z*tanha(q4.z+k4.z)+vv.w*tanha(q4.w+k4.w);
                }
                acc=warp_sum(acc);
                if(lane==0) g_scores[ab*Tv+t_]=acc+vb0;
            }
        }
        sub_barrier(sub_k, tid, ab, sub); sub_k++;

        // ======== P2: softmax + partial ctx ========
        if(wid==0){
            float scv[8], m=-1e30f;
#pragma unroll
            for(int j=0;j<8;j++){ scv[j]=g_scores[ab*Tv+lane+j*32]; m=fmaxf(m,scv[j]); }
            m=warp_max(m);
            float su=0.f;
#pragma unroll
            for(int j=0;j<8;j++) su+=expf(scv[j]-m);
            su=warp_sum(su);
            if(lane==0){ sm[SM_SST]=m; sm[SM_SST+1]=su; }
        }
        if(tid<64) g_ctx[pn][blk*64+tid]=0.f;
        __syncthreads();
        if(tid<32) sm[SM_SW+tid]=expf(g_scores[ab*Tv+t0+tid]-sm[SM_SST])/sm[SM_SST+1];
        __syncthreads();
        {
            const int h2=tid*2;
            float a0=0.f,a1=0.f;
#pragma unroll 8
            for(int j=0;j<32;j++){
                const float wj=sm[SM_SW+j];
                const float2 e2=*(const float2*)(enc+(size_t)(ab*Tv+t0+j)*Hv+h2);
                a0+=wj*e2.x; a1+=wj*e2.y;
            }
            atomicAdd(&g_ctx[p][ab*Hv+h2],a0);
            atomicAdd(&g_ctx[p][ab*Hv+h2+1],a1);
        }

        // ---- pre-stage barrier-independent parts of P3's x (enc, h0_old) ----
        {
            const float4* h0p=(const float4*)g_h[0][p];
            for(int idx=tid; idx<2048; idx+=NTHR){           // enc: k4g 0..127
                const int b_=idx>>7, k4g=idx&127;
                const int kcs=k4g/24, k4=k4g-kcs*24;
                xq4[b_*401+kcs*25+k4]=*(const float4*)(enc+(size_t)(b_*Tv+s)*Hv+k4g*4);
            }
            for(int idx=tid; idx<2048; idx+=NTHR){           // h0_old: k4g 256..383
                const int b_=idx>>7, k4g=256+(idx&127);
                const int kcs=k4g/24, k4=k4g-kcs*24;
                xq4[b_*401+kcs*25+k4]=h0p[b_*128+(idx&127)];
            }
        }
        grid_barrier(bar_k, tid, blk); bar_k++;

        // ======== P3: LSTM layer 0, K=1536 ========
        {
            const float4* ctx=(const float4*)g_ctx[p];
            for(int idx=tid; idx<2048; idx+=NTHR){           // ctx: k4g 128..255
                const int b_=idx>>7, k4g=128+(idx&127);
                const int kcs=k4g/24, k4=k4g-kcs*24;
                xq4[b_*401+kcs*25+k4]=ctx[b_*128+(idx&127)];
            }
        }
        __syncthreads();
        {
            const ulonglong2* wb=(const ulonglong2*)g_W0 + (size_t)(rg*512+blk*4)*384 + kc*24;
            const ulonglong2* xb=(const ulonglong2*)xqu + (bg*4)*401 + kc*25;
            ull acc2[4][4]={};
#pragma unroll 2
            for(int k4=0;k4<24;k4++){
                ulonglong2 xv[4], wv[4];
#pragma unroll
                for(int j=0;j<4;j++) xv[j]=xb[j*401+k4];
#pragma unroll
                for(int i=0;i<4;i++) wv[i]=wb[(size_t)i*384+k4];
#pragma unroll
                for(int i=0;i<4;i++)
#pragma unroll
                    for(int j=0;j<4;j++){
                        fma2(acc2[i][j], wv[i].x, xv[j].x);
                        fma2(acc2[i][j], wv[i].y, xv[j].y);
                    }
            }
            float* red = sm+SM_RED+kc*256;
#pragma unroll
            for(int i=0;i<4;i++)
                *(float4*)(red+(rg*4+i)*16+bg*4)=make_float4(unpack_add(acc2[i][0]),unpack_add(acc2[i][1]),
                                                             unpack_add(acc2[i][2]),unpack_add(acc2[i][3]));
        }
        __syncthreads();
        {
            const int r16=tid>>4, b_=tid&15;
            float g=0.f;
#pragma unroll
            for(int kk=0;kk<16;kk++) g+=sm[SM_RED+kk*256+r16*16+b_];
            const int grow=(r16>>2)*512+blk*4+(r16&3);
            sm[SM_SG+tid]=g+bih0[grow]+bhh0[grow];
        }
        __syncthreads();
        if(tid<64){
            const float gi=sm[SM_SG+(0+ul64)*16+b64], gf=sm[SM_SG+(4+ul64)*16+b64];
            const float gg=sm[SM_SG+(8+ul64)*16+b64], go=sm[SM_SG+(12+ul64)*16+b64];
            c0r=sigf(gf)*c0r+sigf(gi)*tanhf(gg);
            g_h[0][pn][b64*Hv+unit64]=sigf(go)*tanhf(c0r);
        }
        __syncthreads();
        // ---- pre-stage h1_old part of P4's x ----
        {
            const float4* h1o=(const float4*)g_h[1][p];
            for(int idx=tid; idx<2048; idx+=NTHR){           // k4g 128..255
                const int b_=idx>>7, k4g=128+(idx&127);
                const int kcs=k4g>>4, k4=k4g&15;
                xq4[b_*273+kcs*17+k4]=h1o[b_*128+(idx&127)];
            }
        }
        grid_barrier(bar_k, tid, blk); bar_k++;

        // ======== P4: LSTM layer 1, K=1024 ========
        {
            const float4* h0n=(const float4*)g_h[0][pn];
            for(int idx=tid; idx<2048; idx+=NTHR){           // k4g 0..127
                const int b_=idx>>7, k4g=idx&127;
                const int kcs=k4g>>4, k4=k4g&15;
                xq4[b_*273+kcs*17+k4]=h0n[b_*128+k4g];
            }
        }
        __syncthreads();
        {
            const ulonglong2* wb=(const ulonglong2*)g_W1 + (size_t)(rg*512+blk*4)*256 + kc*16;
            const ulonglong2* xb=(const ulonglong2*)xqu + (bg*4)*273 + kc*17;
            ull acc2[4][4]={};
#pragma unroll 2
            for(int k4=0;k4<16;k4++){
                ulonglong2 xv[4], wv[4];
#pragma unroll
                for(int j=0;j<4;j++) xv[j]=xb[j*273+k4];
#pragma unroll
                for(int i=0;i<4;i++) wv[i]=wb[(size_t)i*256+k4];
#pragma unroll
                for(int i=0;i<4;i++)
#pragma unroll
                    for(int j=0;j<4;j++){
                        fma2(acc2[i][j], wv[i].x, xv[j].x);
                        fma2(acc2[i][j], wv[i].y, xv[j].y);
                    }
            }
            float* red = sm+SM_RED+kc*256;
#pragma unroll
            for(int i=0;i<4;i++)
                *(float4*)(red+(rg*4+i)*16+bg*4)=make_float4(unpack_add(acc2[i][0]),unpack_add(acc2[i][1]),
                                                             unpack_add(acc2[i][2]),unpack_add(acc2[i][3]));
        }
        __syncthreads();
        {
            const int r16=tid>>4, b_=tid&15;
            float g=0.f;
#pragma unroll
            for(int kk=0;kk<16;kk++) g+=sm[SM_RED+kk*256+r16*16+b_];
            const int grow=(r16>>2)*512+blk*4+(r16&3);
            sm[SM_SG+tid]=g+bih1[grow]+bhh1[grow];
        }
        __syncthreads();
        if(tid<64){
            const float gi=sm[SM_SG+(0+ul64)*16+b64], gf=sm[SM_SG+(4+ul64)*16+b64];
            const float gg=sm[SM_SG+(8+ul64)*16+b64], go=sm[SM_SG+(12+ul64)*16+b64];
            c1r=sigf(gf)*c1r+sigf(gi)*tanhf(gg);
            g_h[1][pn][b64*Hv+unit64]=sigf(go)*tanhf(c1r);
        }
        grid_barrier(bar_k, tid, blk); bar_k++;

        // ======== P5: qp (next step) + logits ========
        {
            const int bneed=blk>>3;
            const float4* h1n4=(const float4*)g_h[1][pn];
            if(tid<128) xq4[tid]=h1n4[bneed*128+tid];
            __syncthreads();
#pragma unroll
            for(int j=0;j<8;j++){
                const int h=(blk&7)*64+wid*8+j;
                const float4* wq4=(const float4*)(Wq+(size_t)h*Hv);
                float acc=0.f;
#pragma unroll
                for(int i=0;i<4;i++){
                    float4 w4=wq4[i*32+lane], x4=xq4[i*32+lane];
                    acc+=w4.x*x4.x+w4.y*x4.y+w4.z*x4.z+w4.w*x4.w;
                }
                acc=warp_sum(acc);
                if(lane==0) g_qp[bneed*Hv+h]=acc+bq[h];
            }
            if(wid<4){
                const int vo=(blk&7)*4+wid;
                const float4* wo4=(const float4*)(Wout+(size_t)vo*Hv);
                float acc=0.f;
#pragma unroll
                for(int i=0;i<4;i++){
                    float4 w4=wo4[i*32+lane], x4=xq4[i*32+lane];
                    acc+=w4.x*x4.x+w4.y*x4.y+w4.z*x4.z+w4.w*x4.w;
                }
                acc=warp_sum(acc);
                if(lane==0) out[(size_t)(bneed*Tv+s)*Vv+vo]=acc+bout[vo];
            }
        }
        grid_barrier(bar_k, tid, blk); bar_k++;
    }
}

extern "C" void kernel_launch(void* const* d_in, const int* in_sizes, int n_in,
                              void* d_out, int out_size){
    const float* enc  =(const float*)d_in[0];
    const float* h0in =(const float*)d_in[1];
    const float* c0in =(const float*)d_in[2];
    const float* Wq   =(const float*)d_in[4];
    const float* bq   =(const float*)d_in[5];
    const float* Wk   =(const float*)d_in[6];
    const float* bk   =(const float*)d_in[7];
    const float* v    =(const float*)d_in[8];
    const float* vb   =(const float*)d_in[9];
    const float* Wih0 =(const float*)d_in[10];
    const float* bih0 =(const float*)d_in[11];
    const float* Whh0 =(const float*)d_in[12];
    const float* bhh0 =(const float*)d_in[13];
    const float* Wih1 =(const float*)d_in[14];
    const float* bih1 =(const float*)d_in[15];
    const float* Whh1 =(const float*)d_in[16];
    const float* bhh1 =(const float*)d_in[17];
    const float* Wout =(const float*)d_in[18];
    const float* bout =(const float*)d_in[19];
    float* out=(float*)d_out;

    const int smem_bytes = SMEM_FLOATS*4;
    cudaFuncSetAttribute(decoder_main, cudaFuncAttributeMaxDynamicSharedMemorySize, smem_bytes);

    wcat_kernel<<<2048,128>>>(Wih0,Whh0,Wih1,Whh1);
    kproj_kernel<<<dim3(64,8),NTHR>>>(enc,Wk,bk);
    decoder_init<<<NBLK,NTHR>>>(h0in,Wq,bq);
    decoder_main<<<NBLK,NTHR,smem_bytes>>>(enc,c0in,Wq,bq,v,vb,
        bih0,bhh0,bih1,bhh1,Wout,bout,out);
}

// round 6
// speedup vs baseline: 1.2545x; 1.2545x over previous
#include <cuda_runtime.h>
#include <math.h>

#define Bv 16
#define Tv 256
#define Hv 512
#define Vv 32
#define NBLK 128
#define NTHR 256

// smem layout (floats)
#define SM_XQ   0
#define SM_RED  25664            // 16*1604 (P3 xq: 16 rows * 401 float4)
#define SM_SG   (25664+4096)
#define SM_SQ   (SM_SG+256)
#define SM_SV   (SM_SQ+512)
#define SM_SW   (SM_SV+512)
#define SM_SST  (SM_SW+32)
#define SMEM_FLOATS (SM_SST+2)

__device__ float g_W0[2048*1536];     // [Wih0 | Whh0]
__device__ float g_W1[2048*1024];     // [Wih1 | Whh1]
__device__ float g_Kproj[Bv*Tv*Hv];
__device__ float g_qp[Bv*Hv];
__device__ float g_scores[Bv*Tv];
__device__ float g_ctx[2][Bv*Hv];
__device__ float g_h[2][2][Bv*Hv];    // [layer][parity][b*H+h]
__device__ unsigned g_cnt;            // grid barrier arrival counter (monotonic)
__device__ unsigned g_gen;            // grid barrier generation flag
__device__ unsigned g_scnt[Bv];       // sub-barrier counters
__device__ unsigned g_sgen[Bv];       // sub-barrier generations

__device__ __forceinline__ float warp_sum(float v){
#pragma unroll
    for(int o=16;o>0;o>>=1) v += __shfl_xor_sync(0xffffffffu,v,o);
    return v;
}
__device__ __forceinline__ float warp_max(float v){
#pragma unroll
    for(int o=16;o>0;o>>=1) v = fmaxf(v,__shfl_xor_sync(0xffffffffu,v,o));
    return v;
}
__device__ __forceinline__ float sigf(float x){ return 1.0f/(1.0f+expf(-x)); }
__device__ __forceinline__ float tanha(float x){ float y; asm("tanh.approx.f32 %0,%1;":"=f"(y):"f"(x)); return y; }
__device__ __forceinline__ unsigned ld_acq(const unsigned* p){
    unsigned v; asm volatile("ld.acquire.gpu.global.u32 %0,[%1];":"=r"(v):"l"(p):"memory"); return v;
}
__device__ __forceinline__ unsigned atom_add_acqrel(unsigned* p, unsigned v){
    unsigned old; asm volatile("atom.acq_rel.gpu.global.add.u32 %0,[%1],%2;":"=r"(old):"l"(p),"r"(v):"memory"); return old;
}
__device__ __forceinline__ void st_rel(unsigned* p, unsigned v){
    asm volatile("st.release.gpu.global.u32 [%0],%1;"::"l"(p),"r"(v):"memory");
}

// counter/generation grid barrier: write-contended line separated from read-spun line
__device__ __forceinline__ void grid_barrier(unsigned k, int tid){
    __syncthreads();
    if(tid==0){
        unsigned old = atom_add_acqrel(&g_cnt, 1u);
        if(old == k*(unsigned)NBLK - 1u) st_rel(&g_gen, k);
        while(ld_acq(&g_gen) < k) __nanosleep(32);
    }
    __syncthreads();
}
__device__ __forceinline__ void sub_barrier(unsigned k, int tid, int ab){
    __syncthreads();
    if(tid==0){
        unsigned old = atom_add_acqrel(&g_scnt[ab], 1u);
        if(old == k*8u - 1u) st_rel(&g_sgen[ab], k);
        while(ld_acq(&g_sgen[ab]) < k) __nanosleep(32);
    }
    __syncthreads();
}

// ---------- one-time: concatenate LSTM weights ----------
__global__ void wcat_kernel(const float* __restrict__ Wih0, const float* __restrict__ Whh0,
                            const float* __restrict__ Wih1, const float* __restrict__ Whh1){
    const int row = blockIdx.x, tid = threadIdx.x;
    const float4* a0 = (const float4*)(Wih0 + (size_t)row*1024);
    const float4* b0 = (const float4*)(Whh0 + (size_t)row*512);
    float4* d0 = (float4*)(g_W0 + (size_t)row*1536);
#pragma unroll
    for(int i=0;i<2;i++) d0[tid+i*128] = a0[tid+i*128];
    d0[256+tid] = b0[tid];
    const float4* a1 = (const float4*)(Wih1 + (size_t)row*512);
    const float4* b1 = (const float4*)(Whh1 + (size_t)row*512);
    float4* d1 = (float4*)(g_W1 + (size_t)row*1024);
    d1[tid]     = a1[tid];
    d1[128+tid] = b1[tid];
}

// ---------- Kproj = enc @ Wk^T + bk ----------
__global__ void kproj_kernel(const float* __restrict__ enc, const float* __restrict__ Wk,
                             const float* __restrict__ bk){
    __shared__ float As[16][65], Bs[16][65];
    const int bm = blockIdx.x*64, bn = blockIdx.y*64, tid = threadIdx.x;
    const int tm = (tid/16)*4, tn = (tid%16)*4;
    float acc[4][4] = {};
    for(int k0=0;k0<Hv;k0+=16){
        for(int i=tid;i<64*16;i+=NTHR){
            int m=i>>4,k=i&15;
            As[k][m]=enc[(size_t)(bm+m)*Hv+k0+k];
            Bs[k][m]=Wk [(size_t)(bn+m)*Hv+k0+k];
        }
        __syncthreads();
#pragma unroll
        for(int k=0;k<16;k++){
            float a[4],b[4];
#pragma unroll
            for(int x=0;x<4;x++){ a[x]=As[k][tm+x]; b[x]=Bs[k][tn+x]; }
#pragma unroll
            for(int x=0;x<4;x++)
#pragma unroll
                for(int y=0;y<4;y++) acc[x][y]+=a[x]*b[y];
        }
        __syncthreads();
    }
#pragma unroll
    for(int x=0;x<4;x++)
#pragma unroll
        for(int y=0;y<4;y++)
            g_Kproj[(size_t)(bm+tm+x)*Hv+bn+tn+y]=acc[x][y]+bk[bn+tn+y];
}

// ---------- init ----------
__global__ void decoder_init(const float* __restrict__ h0in,
                             const float* __restrict__ Wq, const float* __restrict__ bq){
    const int tid=threadIdx.x, blk=blockIdx.x, gid=blk*NTHR+tid;
    if(gid<Bv*Hv){
        g_h[0][0][gid]=h0in[gid];
        g_h[1][0][gid]=h0in[Bv*Hv+gid];
        g_ctx[0][gid]=0.f; g_ctx[1][gid]=0.f;
    }
    if(gid==0){ g_cnt=0u; g_gen=0u; }
    if(gid<Bv){ g_scnt[gid]=0u; g_sgen[gid]=0u; }
    const int ab=blk>>3, sub=blk&7, wid=tid>>5, lane=tid&31;
    const float4* h14=(const float4*)(h0in+Bv*Hv+ab*Hv);
#pragma unroll
    for(int r=0;r<8;r++){
        const int hrow=sub*64+r*8+wid;
        const float4* wr=(const float4*)(Wq+(size_t)hrow*Hv);
        float acc=0.f;
#pragma unroll
        for(int i=0;i<4;i++){
            float4 w4=wr[i*32+lane], x4=h14[i*32+lane];
            acc+=w4.x*x4.x+w4.y*x4.y+w4.z*x4.z+w4.w*x4.w;
        }
        acc=warp_sum(acc);
        if(lane==0) g_qp[ab*Hv+hrow]=acc+bq[hrow];
    }
}

// ---------- persistent decoder ----------
__global__ void __launch_bounds__(NTHR,1)
decoder_main(const float* __restrict__ enc, const float* __restrict__ c0in,
             const float* __restrict__ Wq, const float* __restrict__ bq,
             const float* __restrict__ v,  const float* __restrict__ vb,
             const float* __restrict__ bih0, const float* __restrict__ bhh0,
             const float* __restrict__ bih1, const float* __restrict__ bhh1,
             const float* __restrict__ Wout, const float* __restrict__ bout,
             float* __restrict__ out){
    extern __shared__ float sm[];
    float4* xq4 = (float4*)(sm + SM_XQ);

    const int tid=threadIdx.x, blk=blockIdx.x;
    const int wid=tid>>5, lane=tid&31;
    const int ab=blk>>3, sub=blk&7, t0=sub*32;
    unsigned bar_k=1, sub_k=1;

    sm[SM_SV+tid]=v[tid]; sm[SM_SV+tid+256]=v[tid+256];
    const float vb0=vb[0];

    const int kc = tid>>4, rg = (tid>>2)&3, bg = tid&3;
    const int ul64=tid>>4, b64=tid&15, unit64=blk*4+ul64;
    float c0r=0.f, c1r=0.f;
    if(tid<64){
        c0r=c0in[b64*Hv+unit64];
        c1r=c0in[Bv*Hv+b64*Hv+unit64];
    }

    for(int s=0;s<Tv;s++){
        const int p=s&1, pn=p^1;

        // ======== P1: attention scores (ab, t0..t0+31) ========
        sm[SM_SQ+tid]=g_qp[ab*Hv+tid]; sm[SM_SQ+tid+256]=g_qp[ab*Hv+256+tid];
        __syncthreads();
        {
            const float4* sq4=(const float4*)(sm+SM_SQ);
            const float4* sv4=(const float4*)(sm+SM_SV);
#pragma unroll
            for(int r=0;r<4;r++){
                const int t_=t0+r*8+wid;
                const float4* kp4=(const float4*)(g_Kproj+(size_t)(ab*Tv+t_)*Hv);
                float acc=0.f;
#pragma unroll
                for(int i=0;i<4;i++){
                    float4 k4=kp4[i*32+lane], q4=sq4[i*32+lane], vv=sv4[i*32+lane];
                    acc+=vv.x*tanha(q4.x+k4.x)+vv.y*tanha(q4.y+k4.y)
                        +vv.z*tanha(q4.z+k4.z)+vv.w*tanha(q4.w+k4.w);
                }
                acc=warp_sum(acc);
                if(lane==0) g_scores[ab*Tv+t_]=acc+vb0;
            }
        }
        sub_barrier(sub_k, tid, ab); sub_k++;

        // ======== P2: softmax + partial ctx ========
        if(wid==0){
            float scv[8], m=-1e30f;
#pragma unroll
            for(int j=0;j<8;j++){ scv[j]=g_scores[ab*Tv+lane+j*32]; m=fmaxf(m,scv[j]); }
            m=warp_max(m);
            float su=0.f;
#pragma unroll
            for(int j=0;j<8;j++) su+=expf(scv[j]-m);
            su=warp_sum(su);
            if(lane==0){ sm[SM_SST]=m; sm[SM_SST+1]=su; }
        }
        if(tid<64) g_ctx[pn][blk*64+tid]=0.f;
        __syncthreads();
        if(tid<32) sm[SM_SW+tid]=expf(g_scores[ab*Tv+t0+tid]-sm[SM_SST])/sm[SM_SST+1];
        __syncthreads();
        {
            const int h2=tid*2;
            float a0=0.f,a1=0.f;
#pragma unroll 8
            for(int j=0;j<32;j++){
                const float wj=sm[SM_SW+j];
                const float2 e2=*(const float2*)(enc+(size_t)(ab*Tv+t0+j)*Hv+h2);
                a0+=wj*e2.x; a1+=wj*e2.y;
            }
            atomicAdd(&g_ctx[p][ab*Hv+h2],a0);
            atomicAdd(&g_ctx[p][ab*Hv+h2+1],a1);
        }

        // ---- pre-stage barrier-independent parts of P3's x (enc, h0_old) ----
        {
            const float4* h0p=(const float4*)g_h[0][p];
            for(int idx=tid; idx<2048; idx+=NTHR){           // enc: k4g 0..127
                const int b_=idx>>7, k4g=idx&127;
                const int kcs=k4g/24, k4=k4g-kcs*24;
                xq4[b_*401+kcs*25+k4]=*(const float4*)(enc+(size_t)(b_*Tv+s)*Hv+k4g*4);
            }
            for(int idx=tid; idx<2048; idx+=NTHR){           // h0_old: k4g 256..383
                const int b_=idx>>7, k4g=256+(idx&127);
                const int kcs=k4g/24, k4=k4g-kcs*24;
                xq4[b_*401+kcs*25+k4]=h0p[b_*128+(idx&127)];
            }
        }
        grid_barrier(bar_k, tid); bar_k++;

        // ======== P3: LSTM layer 0, K=1536 ========
        {
            const float4* ctx=(const float4*)g_ctx[p];
            for(int idx=tid; idx<2048; idx+=NTHR){           // ctx: k4g 128..255
                const int b_=idx>>7, k4g=128+(idx&127);
                const int kcs=k4g/24, k4=k4g-kcs*24;
                xq4[b_*401+kcs*25+k4]=ctx[b_*128+(idx&127)];
            }
        }
        __syncthreads();
        {
            const float4* wb=(const float4*)g_W0 + (size_t)(rg*512+blk*4)*384 + kc*24;
            const float4* xb=xq4 + (bg*4)*401 + kc*25;
            float acc[4][4]={};
#pragma unroll 4
            for(int k4=0;k4<24;k4++){
                float4 xv[4], wv[4];
#pragma unroll
                for(int j=0;j<4;j++) xv[j]=xb[j*401+k4];
#pragma unroll
                for(int i=0;i<4;i++) wv[i]=wb[(size_t)i*384+k4];
#pragma unroll
                for(int i=0;i<4;i++)
#pragma unroll
                    for(int j=0;j<4;j++)
                        acc[i][j]+=wv[i].x*xv[j].x+wv[i].y*xv[j].y+wv[i].z*xv[j].z+wv[i].w*xv[j].w;
            }
            float* red = sm+SM_RED+kc*256;
#pragma unroll
            for(int i=0;i<4;i++)
                *(float4*)(red+(rg*4+i)*16+bg*4)=make_float4(acc[i][0],acc[i][1],acc[i][2],acc[i][3]);
        }
        __syncthreads();
        {
            const int r16=tid>>4, b_=tid&15;
            float g=0.f;
#pragma unroll
            for(int kk=0;kk<16;kk++) g+=sm[SM_RED+kk*256+r16*16+b_];
            const int grow=(r16>>2)*512+blk*4+(r16&3);
            sm[SM_SG+tid]=g+bih0[grow]+bhh0[grow];
        }
        __syncthreads();
        if(tid<64){
            const float gi=sm[SM_SG+(0+ul64)*16+b64], gf=sm[SM_SG+(4+ul64)*16+b64];
            const float gg=sm[SM_SG+(8+ul64)*16+b64], go=sm[SM_SG+(12+ul64)*16+b64];
            c0r=sigf(gf)*c0r+sigf(gi)*tanhf(gg);
            g_h[0][pn][b64*Hv+unit64]=sigf(go)*tanhf(c0r);
        }
        __syncthreads();
        // ---- pre-stage h1_old part of P4's x ----
        {
            const float4* h1o=(const float4*)g_h[1][p];
            for(int idx=tid; idx<2048; idx+=NTHR){           // k4g 128..255
                const int b_=idx>>7, k4g=128+(idx&127);
                const int kcs=k4g>>4, k4=k4g&15;
                xq4[b_*273+kcs*17+k4]=h1o[b_*128+(idx&127)];
            }
        }
        grid_barrier(bar_k, tid); bar_k++;

        // ======== P4: LSTM layer 1, K=1024 ========
        {
            const float4* h0n=(const float4*)g_h[0][pn];
            for(int idx=tid; idx<2048; idx+=NTHR){           // k4g 0..127
                const int b_=idx>>7, k4g=idx&127;
                const int kcs=k4g>>4, k4=k4g&15;
                xq4[b_*273+kcs*17+k4]=h0n[b_*128+k4g];
            }
        }
        __syncthreads();
        {
            const float4* wb=(const float4*)g_W1 + (size_t)(rg*512+blk*4)*256 + kc*16;
            const float4* xb=xq4 + (bg*4)*273 + kc*17;
            float acc[4][4]={};
#pragma unroll 4
            for(int k4=0;k4<16;k4++){
                float4 xv[4], wv[4];
#pragma unroll
                for(int j=0;j<4;j++) xv[j]=xb[j*273+k4];
#pragma unroll
                for(int i=0;i<4;i++) wv[i]=wb[(size_t)i*256+k4];
#pragma unroll
                for(int i=0;i<4;i++)
#pragma unroll
                    for(int j=0;j<4;j++)
                        acc[i][j]+=wv[i].x*xv[j].x+wv[i].y*xv[j].y+wv[i].z*xv[j].z+wv[i].w*xv[j].w;
            }
            float* red = sm+SM_RED+kc*256;
#pragma unroll
            for(int i=0;i<4;i++)
                *(float4*)(red+(rg*4+i)*16+bg*4)=make_float4(acc[i][0],acc[i][1],acc[i][2],acc[i][3]);
        }
        __syncthreads();
        {
            const int r16=tid>>4, b_=tid&15;
            float g=0.f;
#pragma unroll
            for(int kk=0;kk<16;kk++) g+=sm[SM_RED+kk*256+r16*16+b_];
            const int grow=(r16>>2)*512+blk*4+(r16&3);
            sm[SM_SG+tid]=g+bih1[grow]+bhh1[grow];
        }
        __syncthreads();
        if(tid<64){
            const float gi=sm[SM_SG+(0+ul64)*16+b64], gf=sm[SM_SG+(4+ul64)*16+b64];
            const float gg=sm[SM_SG+(8+ul64)*16+b64], go=sm[SM_SG+(12+ul64)*16+b64];
            c1r=sigf(gf)*c1r+sigf(gi)*tanhf(gg);
            g_h[1][pn][b64*Hv+unit64]=sigf(go)*tanhf(c1r);
        }
        grid_barrier(bar_k, tid); bar_k++;

        // ======== P5: qp (next step) + logits ========
        {
            const int bneed=blk>>3;
            const float4* h1n4=(const float4*)g_h[1][pn];
            if(tid<128) xq4[tid]=h1n4[bneed*128+tid];
            __syncthreads();
#pragma unroll
            for(int j=0;j<8;j++){
                const int h=(blk&7)*64+wid*8+j;
                const float4* wq4=(const float4*)(Wq+(size_t)h*Hv);
                float acc=0.f;
#pragma unroll
                for(int i=0;i<4;i++){
                    float4 w4=wq4[i*32+lane], x4=xq4[i*32+lane];
                    acc+=w4.x*x4.x+w4.y*x4.y+w4.z*x4.z+w4.w*x4.w;
                }
                acc=warp_sum(acc);
                if(lane==0) g_qp[bneed*Hv+h]=acc+bq[h];
            }
            if(wid<4){
                const int vo=(blk&7)*4+wid;
                const float4* wo4=(const float4*)(Wout+(size_t)vo*Hv);
                float acc=0.f;
#pragma unroll
                for(int i=0;i<4;i++){
                    float4 w4=wo4[i*32+lane], x4=xq4[i*32+lane];
                    acc+=w4.x*x4.x+w4.y*x4.y+w4.z*x4.z+w4.w*x4.w;
                }
                acc=warp_sum(acc);
                if(lane==0) out[(size_t)(bneed*Tv+s)*Vv+vo]=acc+bout[vo];
            }
        }
        grid_barrier(bar_k, tid); bar_k++;
    }
}

extern "C" void kernel_launch(void* const* d_in, const int* in_sizes, int n_in,
                              void* d_out, int out_size){
    const float* enc  =(const float*)d_in[0];
    const float* h0in =(const float*)d_in[1];
    const float* c0in =(const float*)d_in[2];
    const float* Wq   =(const float*)d_in[4];
    const float* bq   =(const float*)d_in[5];
    const float* Wk   =(const float*)d_in[6];
    const float* bk   =(const float*)d_in[7];
    const float* v    =(const float*)d_in[8];
    const float* vb   =(const float*)d_in[9];
    const float* Wih0 =(const float*)d_in[10];
    const float* bih0 =(const float*)d_in[11];
    const float* Whh0 =(const float*)d_in[12];
    const float* bhh0 =(const float*)d_in[13];
    const float* Wih1 =(const float*)d_in[14];
    const float* bih1 =(const float*)d_in[15];
    const float* Whh1 =(const float*)d_in[16];
    const float* bhh1 =(const float*)d_in[17];
    const float* Wout =(const float*)d_in[18];
    const float* bout =(const float*)d_in[19];
    float* out=(float*)d_out;

    const int smem_bytes = SMEM_FLOATS*4;
    cudaFuncSetAttribute(decoder_main, cudaFuncAttributeMaxDynamicSharedMemorySize, smem_bytes);

    wcat_kernel<<<2048,128>>>(Wih0,Whh0,Wih1,Whh1);
    kproj_kernel<<<dim3(64,8),NTHR>>>(enc,Wk,bk);
    decoder_init<<<NBLK,NTHR>>>(h0in,Wq,bq);
    decoder_main<<<NBLK,NTHR,smem_bytes>>>(enc,c0in,Wq,bq,v,vb,
        bih0,bhh0,bih1,bhh1,Wout,bout,out);
}